// round 4
// baseline (speedup 1.0000x reference)
#include <cuda_runtime.h>

// Problem constants (fixed by dataset)
#define NIMG 8
#define NCLS 21
#define NPIX 262144      // 512*512, = 2^18
#define NDIM 32
#define IGNORE_LAB 255
#define PSHIFT 18

// Scratch (no allocation allowed -> __device__ globals)
__device__ float  g_sums[NIMG * NCLS * NDIM];   // per-(n,c) feature sums
__device__ float  g_counts[NIMG * NCLS];        // per-(n,c) valid counts
__device__ double g_scal[6];                    // 0:ce 1:validcnt 2:var 3:inter 4:sumsq

// ---------------------------------------------------------------------------
// Kernel 0: zero all scratch (graph replays re-run this each launch)
// ---------------------------------------------------------------------------
__global__ void k_zero() {
    int i = blockIdx.x * blockDim.x + threadIdx.x;
    int stride = gridDim.x * blockDim.x;
    for (int idx = i; idx < NIMG * NCLS * NDIM; idx += stride) g_sums[idx] = 0.f;
    if (i < NIMG * NCLS) g_counts[i] = 0.f;
    if (i < 6) g_scal[i] = 0.0;
}

// ---------------------------------------------------------------------------
// Kernel 1: logit pass.  One pixel per thread (grid-stride).
// Accumulates: ce numerator (lse - logit[label]), valid count, -logit[label],
// (sum_c logit - logit[label]).
// ---------------------------------------------------------------------------
__global__ __launch_bounds__(256) void k_logit(const float* __restrict__ logit,
                                               const int* __restrict__ target) {
    int tid = blockIdx.x * blockDim.x + threadIdx.x;
    int stride = gridDim.x * blockDim.x;

    float ce = 0.f, cnt = 0.f, var = 0.f, inter = 0.f;

    for (int g = tid; g < NIMG * NPIX; g += stride) {
        int n = g >> PSHIFT;
        int p = g & (NPIX - 1);
        const float* lp = logit + (size_t)n * NCLS * NPIX + p;

        float v[NCLS];
#pragma unroll
        for (int c = 0; c < NCLS; c++) v[c] = __ldg(lp + (size_t)c * NPIX);

        float m = v[0];
#pragma unroll
        for (int c = 1; c < NCLS; c++) m = fmaxf(m, v[c]);

        float s = 0.f, tot = 0.f;
#pragma unroll
        for (int c = 0; c < NCLS; c++) {
            s += __expf(v[c] - m);
            tot += v[c];
        }
        float lse = m + __logf(s);

        int lab = __ldg(target + g);
        if (lab != IGNORE_LAB) {
            // predicated select keeps v[] in registers (no dynamic indexing)
            float lg = v[0];
#pragma unroll
            for (int c = 1; c < NCLS; c++) lg = (c == lab) ? v[c] : lg;
            ce += (lse - lg);
            cnt += 1.f;
            var -= lg;
            inter += (tot - lg);
        }
    }

    // block reduction of 4 scalars
    int lane = threadIdx.x & 31;
    int wid = threadIdx.x >> 5;
#pragma unroll
    for (int o = 16; o > 0; o >>= 1) {
        ce += __shfl_down_sync(0xffffffffu, ce, o);
        cnt += __shfl_down_sync(0xffffffffu, cnt, o);
        var += __shfl_down_sync(0xffffffffu, var, o);
        inter += __shfl_down_sync(0xffffffffu, inter, o);
    }
    __shared__ float sred[4][8];
    if (lane == 0) {
        sred[0][wid] = ce; sred[1][wid] = cnt; sred[2][wid] = var; sred[3][wid] = inter;
    }
    __syncthreads();
    if (threadIdx.x == 0) {
        float a = 0, b = 0, c2 = 0, d2 = 0;
#pragma unroll
        for (int w = 0; w < 8; w++) {
            a += sred[0][w]; b += sred[1][w]; c2 += sred[2][w]; d2 += sred[3][w];
        }
        atomicAdd(&g_scal[0], (double)a);
        atomicAdd(&g_scal[1], (double)b);
        atomicAdd(&g_scal[2], (double)c2);
        atomicAdd(&g_scal[3], (double)d2);
    }
}

// ---------------------------------------------------------------------------
// Kernel 2: feature pass.  Warp processes a contiguous pixel chunk of one
// image; lane l exclusively owns feature dim l -> race-free warp-private
// smem accumulation, no atomics in the hot loop.
// grid = (BLOCKS_PER_IMG, NIMG), 256 threads (8 warps).
// ---------------------------------------------------------------------------
#define BLOCKS_PER_IMG 128
#define WARPS_PER_BLK 8
#define PIX_PER_WARP (NPIX / (BLOCKS_PER_IMG * WARPS_PER_BLK))   // 256

__global__ __launch_bounds__(256) void k_feat(const float* __restrict__ feat,
                                              const int* __restrict__ target) {
    __shared__ float acc[WARPS_PER_BLK][NCLS * NDIM];  // 8*672*4 = 21504 B
    __shared__ float csh[WARPS_PER_BLK][32];           // counts (padded), 1 KB

    int lane = threadIdx.x & 31;
    int wid = threadIdx.x >> 5;
    int n = blockIdx.y;

    for (int idx = threadIdx.x; idx < WARPS_PER_BLK * NCLS * NDIM; idx += blockDim.x)
        (&acc[0][0])[idx] = 0.f;
    (&csh[0][0])[threadIdx.x] = 0.f;   // 256 = 8*32 exactly
    __syncthreads();

    int p0 = (blockIdx.x * WARPS_PER_BLK + wid) * PIX_PER_WARP;
    const int* tg = target + (size_t)n * NPIX;
    const float* fp = feat + (size_t)n * NPIX * NDIM;

    float ssq = 0.f;
    float* myacc = &acc[wid][0];
    float* mycnt = &csh[wid][0];

#pragma unroll 1
    for (int p = p0; p < p0 + PIX_PER_WARP; p += 4) {
        // batch loads for MLP
        int l0 = tg[p + 0], l1 = tg[p + 1], l2 = tg[p + 2], l3 = tg[p + 3];
        float f0 = fp[(size_t)(p + 0) * NDIM + lane];
        float f1 = fp[(size_t)(p + 1) * NDIM + lane];
        float f2 = fp[(size_t)(p + 2) * NDIM + lane];
        float f3 = fp[(size_t)(p + 3) * NDIM + lane];

        if (l0 != IGNORE_LAB) {
            myacc[l0 * NDIM + lane] += f0; ssq += f0 * f0;
            if (lane == 0) mycnt[l0] += 1.f;
        }
        if (l1 != IGNORE_LAB) {
            myacc[l1 * NDIM + lane] += f1; ssq += f1 * f1;
            if (lane == 0) mycnt[l1] += 1.f;
        }
        if (l2 != IGNORE_LAB) {
            myacc[l2 * NDIM + lane] += f2; ssq += f2 * f2;
            if (lane == 0) mycnt[l2] += 1.f;
        }
        if (l3 != IGNORE_LAB) {
            myacc[l3 * NDIM + lane] += f3; ssq += f3 * f3;
            if (lane == 0) mycnt[l3] += 1.f;
        }
    }
    __syncthreads();

    // combine 8 warp buffers -> global (672 REDG per block)
    for (int idx = threadIdx.x; idx < NCLS * NDIM; idx += blockDim.x) {
        float s = 0.f;
#pragma unroll
        for (int w = 0; w < WARPS_PER_BLK; w++) s += acc[w][idx];
        atomicAdd(&g_sums[(size_t)n * NCLS * NDIM + idx], s);
    }
    if (threadIdx.x < NCLS) {
        float s = 0.f;
#pragma unroll
        for (int w = 0; w < WARPS_PER_BLK; w++) s += csh[w][threadIdx.x];
        atomicAdd(&g_counts[n * NCLS + threadIdx.x], s);
    }

    // reduce ssq across block
#pragma unroll
    for (int o = 16; o > 0; o >>= 1) ssq += __shfl_down_sync(0xffffffffu, ssq, o);
    __shared__ float sq[8];
    if (lane == 0) sq[wid] = ssq;
    __syncthreads();
    if (threadIdx.x == 0) {
        float s = 0.f;
#pragma unroll
        for (int w = 0; w < WARPS_PER_BLK; w++) s += sq[w];
        atomicAdd(&g_scal[4], (double)s);
    }
}

// ---------------------------------------------------------------------------
// Kernel 3: finalize.  Single block; per-(n,c) mean term + combine scalars.
// ---------------------------------------------------------------------------
__global__ void k_final(float* __restrict__ out) {
    __shared__ double red[256];
    int tid = threadIdx.x;

    double center_neg = 0.0;   // accumulates -||sums||^2/count over (n,c)
    for (int i = tid; i < NIMG * NCLS; i += 256) {
        double cntv = (double)g_counts[i];
        if (cntv > 0.0) {
            double m2 = 0.0;
            const float* s = &g_sums[(size_t)i * NDIM];
#pragma unroll
            for (int d = 0; d < NDIM; d++) m2 += (double)s[d] * (double)s[d];
            center_neg -= m2 / cntv;
        }
    }
    red[tid] = center_neg;
    __syncthreads();
    for (int o = 128; o > 0; o >>= 1) {
        if (tid < o) red[tid] += red[tid + o];
        __syncthreads();
    }
    if (tid == 0) {
        double denom = g_scal[1] > 1.0 ? g_scal[1] : 1.0;
        double CE = g_scal[0] / denom;
        double VAR = g_scal[2] / (double)NPIX;
        double Inter = g_scal[3] / (double)NPIX;
        double Center = (g_scal[4] + red[0]) / (double)NPIX;
        double loss = (CE + 1.0 * VAR + 0.5 * Inter + 0.1 * Center) / (double)NIMG;
        out[0] = (float)loss;
    }
}

// ---------------------------------------------------------------------------
extern "C" void kernel_launch(void* const* d_in, const int* in_sizes, int n_in,
                              void* d_out, int out_size) {
    const float* logit = (const float*)d_in[0];
    const int* target = (const int*)d_in[1];
    const float* feat = (const float*)d_in[2];
    float* out = (float*)d_out;

    k_zero<<<24, 256>>>();
    k_logit<<<1184, 256>>>(logit, target);
    k_feat<<<dim3(BLOCKS_PER_IMG, NIMG), 256>>>(feat, target);
    k_final<<<1, 256>>>(out);
}